// round 7
// baseline (speedup 1.0000x reference)
#include <cuda_runtime.h>
#include <cstdint>

#define B_DIM    8
#define C_OUT    64
#define NK       7
#define GROUP_IN 4
#define C_IN     1792              // 64*4*7
#define L_DIM    4096
#define TILE     128
#define HALO     16                // covers |shift| <= 15, 16B-aligned halo
#define ROWW     (TILE + 2*HALO)   // 160 floats per staged row
#define NCH      (GROUP_IN * NK)   // 28 channels per c_out
#define THREADS  256
#define CTAS_SM  5
#define GRID     (152 * CTAS_SM)   // 760: 5 persistent CTAs per GB300 SM
#define NTILES   (B_DIM * C_OUT * (L_DIM / TILE))   // 16384 work items
#define BUFSZ    (NCH * ROWW)      // 4480 floats per tile buffer (17920 B)
#define NVEC     (ROWW / 4)        // 40 chunks per row
#define INT_CHUNKS (NCH * (TILE / 4))   // 896 interior chunks

// 16B async copy global->shared; src_size==0 -> zero-fill (implements the
// roll's zero padding: OOB regions are always whole 16B chunks).
__device__ __forceinline__ void cp_async16(uint32_t dst, const void* src, int sz) {
    asm volatile("cp.async.cg.shared.global [%0], [%1], 16, %2;\n"
                 :: "r"(dst), "l"(src), "r"(sz));
}
__device__ __forceinline__ void cp_commit() {
    asm volatile("cp.async.commit_group;\n" ::: "memory");
}
__device__ __forceinline__ void cp_wait1() {
    asm volatile("cp.async.wait_group 1;\n" ::: "memory");
}

__global__ __launch_bounds__(THREADS, CTAS_SM) void addshift_kernel(
    const float* __restrict__ x,
    const int*   __restrict__ si1,
    const int*   __restrict__ si2,
    const int*   __restrict__ si3,
    float*       __restrict__ out)
{
    extern __shared__ float sm[];              // [2][NCH][ROWW]
    __shared__ unsigned tab[C_OUT * NCH];      // packed per-(co,lc) byte offsets
    __shared__ int      crel[NCH];             // channel offset (elems) per local row

    const int tid = threadIdx.x;
    const uint32_t sm_base = (uint32_t)__cvta_generic_to_shared(sm);

    // ---- one-time tables ----
    // crel[lc]: global-channel element offset of local row lc (co-independent)
    if (tid < NCH)
        crel[tid] = ((tid / NK) * (C_OUT * NK) + (tid % NK)) * L_DIM;
    // tab: in-row byte offset = (1 + 5*(idx%7))*4, three 8-bit fields (<=124)
    for (int c = tid; c < C_IN; c += THREADS) {
        int g  = c / (C_OUT * NK);
        int r  = c - g * (C_OUT * NK);
        int co = r / NK;
        int k  = r - co * NK;
        int lc = g * NK + k;
        unsigned o1 = 4u + 20u * (unsigned)(si1[c] % NK);
        unsigned o2 = 4u + 20u * (unsigned)(si2[c] % NK);
        unsigned o3 = 4u + 20u * (unsigned)(si3[c] % NK);
        tab[co * NCH + lc] = o1 | (o2 << 8) | (o3 << 16);
    }
    __syncthreads();   // crel needed by the prologue stage below

    const size_t OSZ = (size_t)B_DIM * C_OUT * L_DIM;   // one output tensor

    // ---- tile stager (lambda): 28 rows x 160 floats into smem at smbuf ----
    auto stage_tile = [&](int w, uint32_t smbuf) {
        const int b   = w >> 11;            // C_OUT * 32 tiles per batch
        const int rem = w & 2047;
        const int co  = rem >> 5;
        const int tx  = rem & 31;
        const int gstart = (tx << 7) - HALO;
        const float* base = x + ((size_t)b * C_IN + (size_t)co * NK) * L_DIM + gstart;

        // interior: 896 chunks, window [t0, t0+128) always in-bounds
        #pragma unroll
        for (int i = 0; i < INT_CHUNKS / THREADS; ++i) {          // 3 full passes
            int idx = tid + i * THREADS;
            unsigned lc = (unsigned)idx >> 5;                     // 0..27
            unsigned j4 = ((unsigned)idx & 31u) * 4u + HALO;      // [16,144)
            cp_async16(smbuf + (lc * ROWW + j4) * 4u, base + crel[lc] + j4, 16);
        }
        { // remainder pass: chunks 768..895
            int idx = tid + 768;
            if (idx < INT_CHUNKS) {
                unsigned lc = (unsigned)idx >> 5;
                unsigned j4 = ((unsigned)idx & 31u) * 4u + HALO;
                cp_async16(smbuf + (lc * ROWW + j4) * 4u, base + crel[lc] + j4, 16);
            }
        }
        // halo: 28 rows x 8 chunks (4 front, 4 back), edge-guarded / zero-filled
        if (tid < NCH * 8) {
            unsigned lc = (unsigned)tid >> 3;
            unsigned h  = (unsigned)tid & 7u;
            unsigned j4 = (h < 4u) ? h * 4u : (TILE + h * 4u);    // 0..12, 128+..
            int gp = gstart + (int)j4;
            int sz = (gp >= 0 && gp < L_DIM) ? 16 : 0;
            cp_async16(smbuf + (lc * ROWW + j4) * 4u, base + crel[lc] + (int)j4, sz);
        }
    };

    // ---- pipeline prologue ----
    stage_tile(blockIdx.x, sm_base);
    cp_commit();

    int parity = 0;
    for (int w = blockIdx.x; w < NTILES; w += GRID) {
        const int wn = w + GRID;
        if (wn < NTILES)
            stage_tile(wn, sm_base + (uint32_t)((parity ^ 1) * BUFSZ * 4));
        cp_commit();               // empty group on final iteration
        cp_wait1();                // current tile fully landed
        __syncthreads();

        // ---- accumulate tile w from buf[parity]: thread owns t = t0 + tid%128?  ----
        // 256 threads, 128 points: threads 0..127 own t, threads 128..255 own
        // nothing? No — each thread owns ONE point only if THREADS==TILE.
        // Here THREADS=256 > TILE=128: split channels instead. Threads with
        // hi=tid>>7 (0/1) each accumulate 14 channels for point t = t0+(tid&127),
        // then combine via smem.
        const int b   = w >> 11;
        const int rem = w & 2047;
        const int co  = rem >> 5;
        const int tx  = rem & 31;
        const int hi  = tid >> 7;              // channel half: 0 -> lc 0..13, 1 -> 14..27
        const int pt  = tid & 127;             // owned point within tile
        const uint4* tabco = (const uint4*)(tab + co * NCH);
        const char* smb = (const char*)(sm + parity * BUFSZ)
                        + (size_t)((unsigned)(hi * 14 * ROWW + pt) * 4u);

        float a1 = 0.f, a2 = 0.f, a3 = 0.f;
        // 14 channels per half; tab packed as 7 uint4 = 28 words; half hi uses
        // words [hi*14, hi*14+14) -> uint4 indices with manual unpack.
        #pragma unroll
        for (int q = 0; q < 3; ++q) {                  // 3 uint4 = 12 words
            uint4 pw = tabco[hi * 3 + q + hi];          // hi=0: q0..2 (w0..11); hi=1: q4..6 (w16..27)? fix below
            (void)pw;
        }
        // -- simpler correct path: scalar broadcast loads (unrolled) --
        {
            const unsigned* tsc = tab + co * NCH + hi * 14;
            #pragma unroll
            for (int j = 0; j < 14; ++j) {
                unsigned p = tsc[j];
                a1 += *(const float*)(smb + (p & 255u)        + j * (ROWW * 4));
                a2 += *(const float*)(smb + ((p >> 8) & 255u) + j * (ROWW * 4));
                a3 += *(const float*)(smb + (p >> 16)         + j * (ROWW * 4));
            }
        }

        // combine halves: half 1 deposits, half 0 adds and stores
        __shared__ float part[3][TILE];
        if (hi == 1) {
            part[0][pt] = a1; part[1][pt] = a2; part[2][pt] = a3;
        }
        __syncthreads();
        if (hi == 0) {
            a1 += part[0][pt]; a2 += part[1][pt]; a3 += part[2][pt];
            const size_t ob = ((size_t)b * C_OUT + co) * L_DIM + (tx << 7) + pt;
            out[ob]           = a1;
            out[ob + OSZ]     = a2;
            out[ob + 2 * OSZ] = a3;
        }

        __syncthreads();           // buf[parity] + part free for reuse
        parity ^= 1;
    }
}

extern "C" void kernel_launch(void* const* d_in, const int* in_sizes, int n_in,
                              void* d_out, int out_size) {
    const float* x   = (const float*)d_in[0];
    const int*   si1 = (const int*)d_in[1];
    const int*   si2 = (const int*)d_in[2];
    const int*   si3 = (const int*)d_in[3];
    float* out = (float*)d_out;

    const int smem_bytes = 2 * BUFSZ * (int)sizeof(float);    // 35840
    cudaFuncSetAttribute(addshift_kernel,
                         cudaFuncAttributeMaxDynamicSharedMemorySize, smem_bytes);

    addshift_kernel<<<GRID, THREADS, smem_bytes>>>(x, si1, si2, si3, out);
}

// round 8
// speedup vs baseline: 1.2070x; 1.2070x over previous
#include <cuda_runtime.h>
#include <cstdint>

#define B_DIM    8
#define C_OUT    64
#define NK       7
#define GROUP_IN 4
#define C_IN     1792              // 64*4*7
#define L_DIM    4096
#define TILE     256
#define HALO     16                // covers |shift| <= 15
#define ROWW     (TILE + 2*HALO)   // 288 floats per staged row
#define ROWB     (ROWW * 4)        // 1152 bytes per staged row
#define NCH      (GROUP_IN * NK)   // 28 channels per c_out
#define THREADS  256
#define GRID     456               // 3 persistent CTAs per GB300 SM
#define NTILES   (B_DIM * C_OUT * (L_DIM / TILE))   // 8192
#define BUFSZ    (NCH * ROWW)      // 8064 floats per buffer (32256 B)

// --- TMA bulk 1D: global -> shared, mbarrier transaction-counted ---
__device__ __forceinline__ void bulk_g2s(uint32_t dst, const void* src,
                                         unsigned bytes, uint32_t mbar) {
    asm volatile(
        "cp.async.bulk.shared::cluster.global.mbarrier::complete_tx::bytes "
        "[%0], [%1], %2, [%3];"
        :: "r"(dst), "l"(src), "r"(bytes), "r"(mbar) : "memory");
}
__device__ __forceinline__ void mbar_init1(uint32_t mbar) {
    asm volatile("mbarrier.init.shared.b64 [%0], 1;" :: "r"(mbar) : "memory");
}
__device__ __forceinline__ void mbar_expect(uint32_t mbar, unsigned bytes) {
    asm volatile("mbarrier.arrive.expect_tx.shared.b64 _, [%0], %1;"
                 :: "r"(mbar), "r"(bytes) : "memory");
}
__device__ __forceinline__ void mbar_wait(uint32_t mbar, unsigned ph) {
    asm volatile(
        "{\n\t.reg .pred P;\n\t"
        "LAB_%=:\n\t"
        "mbarrier.try_wait.parity.acquire.cta.shared::cta.b64 P, [%0], %1, 0x989680;\n\t"
        "@P bra.uni DONE_%=;\n\t"
        "bra.uni LAB_%=;\n\t"
        "DONE_%=:\n\t}"
        :: "r"(mbar), "r"(ph) : "memory");
}

__global__ __launch_bounds__(THREADS, 3) void addshift_kernel(
    const float* __restrict__ x,
    const int*   __restrict__ si1,
    const int*   __restrict__ si2,
    const int*   __restrict__ si3,
    float*       __restrict__ out)
{
    extern __shared__ float sm[];                    // [2][NCH][ROWW]
    __shared__ unsigned tab[C_OUT * NCH];            // packed per-(co,lc) offsets
    __shared__ __align__(8) unsigned long long mbar_s[2];

    const int tid = threadIdx.x;
    const uint32_t sm_base = (uint32_t)__cvta_generic_to_shared(sm);
    const uint32_t mb0 = (uint32_t)__cvta_generic_to_shared(&mbar_s[0]);
    const uint32_t mb1 = (uint32_t)__cvta_generic_to_shared(&mbar_s[1]);

    // ---- one-time offset table: in-row byte offset = (1 + 5*(idx%7))*4,
    // three 8-bit fields (each <= 124) ----
    for (int c = tid; c < C_IN; c += THREADS) {
        int g  = c / (C_OUT * NK);
        int r  = c - g * (C_OUT * NK);
        int co = r / NK;
        int k  = r - co * NK;
        int lc = g * NK + k;
        unsigned o1 = 4u + 20u * (unsigned)(si1[c] % NK);
        unsigned o2 = 4u + 20u * (unsigned)(si2[c] % NK);
        unsigned o3 = 4u + 20u * (unsigned)(si3[c] % NK);
        tab[co * NCH + lc] = o1 | (o2 << 8) | (o3 << 16);
    }
    if (tid == 0) { mbar_init1(mb0); mbar_init1(mb1); }

    // per-lane staged-row constant: global element offset of local row (tid<28)
    int crel = 0;
    if (tid < NCH) crel = ((tid / NK) * (C_OUT * NK) + tid % NK) * L_DIM;

    __syncthreads();   // tab + mbarrier init visible

    const size_t OSZ = (size_t)B_DIM * C_OUT * L_DIM;   // one output tensor

    // ---- stage one tile: 28 bulk copies (warp 0) + edge zero-fill (all) ----
    auto stage = [&](int w, int bufidx, uint32_t mb) {
        const int b   = w >> 10;                 // 1024 tiles per batch
        const int rem = w & 1023;
        const int co  = rem >> 4;
        const int tx  = rem & 15;
        const int gstart = (tx << 8) - HALO;
        const bool front = (tx == 0);
        const bool back  = (tx == 15);
        const unsigned sz = (front || back) ? (ROWB - 64u) : ROWB;

        if (tid < 32) {
            if (tid == 0) mbar_expect(mb, NCH * sz);
            __syncwarp();
            if (tid < NCH) {
                const float* src = x + ((size_t)b * C_IN + (size_t)co * NK) * L_DIM
                                 + crel + gstart + (front ? HALO : 0);
                uint32_t dst = sm_base + (uint32_t)(bufidx * (BUFSZ * 4))
                             + (uint32_t)tid * ROWB + (front ? 64u : 0u);
                bulk_g2s(dst, src, sz, mb);
            }
        }
        // zero the 16-float OOB halo (disjoint from bulk's bytes)
        if (front || back) {
            float* bp = sm + bufidx * BUFSZ + (front ? 0 : (TILE + HALO));
            for (int i = tid; i < NCH * HALO; i += THREADS) {
                int lc = i >> 4, j = i & 15;
                bp[lc * ROWW + j] = 0.f;
            }
        }
    };

    // ---- pipeline prologue ----
    stage(blockIdx.x, 0, mb0);

    unsigned ph0 = 0, ph1 = 0;
    int parity = 0;
    for (int w = blockIdx.x; w < NTILES; w += GRID) {
        const int wn = w + GRID;
        if (wn < NTILES)
            stage(wn, parity ^ 1, parity ? mb0 : mb1);

        if (parity == 0) { mbar_wait(mb0, ph0); ph0 ^= 1; }
        else             { mbar_wait(mb1, ph1); ph1 ^= 1; }
        __syncthreads();          // bulk data + STS zeros visible to all

        // ---- accumulate tile w from buf[parity]: thread owns t = t0 + tid ----
        const int b   = w >> 10;
        const int rem = w & 1023;
        const int co  = rem >> 4;
        const int tx  = rem & 15;
        const unsigned* tabco = tab + co * NCH;
        const char* smb = (const char*)(sm + parity * BUFSZ)
                        + (size_t)((unsigned)tid * 4u);

        float a1 = 0.f, a2 = 0.f, a3 = 0.f;
        #pragma unroll
        for (int lc = 0; lc < NCH; ++lc) {
            unsigned p = tabco[lc];                    // one LDS.32 broadcast
            a1 += *(const float*)(smb + (p & 255u)        + lc * ROWB);
            a2 += *(const float*)(smb + ((p >> 8) & 255u) + lc * ROWB);
            a3 += *(const float*)(smb + (p >> 16)         + lc * ROWB);
        }

        const size_t ob = ((size_t)b * C_OUT + co) * L_DIM + (tx << 8) + tid;
        out[ob]           = a1;
        out[ob + OSZ]     = a2;
        out[ob + 2 * OSZ] = a3;

        __syncthreads();          // buf[parity] free for restaging
        parity ^= 1;
    }
}

extern "C" void kernel_launch(void* const* d_in, const int* in_sizes, int n_in,
                              void* d_out, int out_size) {
    const float* x   = (const float*)d_in[0];
    const int*   si1 = (const int*)d_in[1];
    const int*   si2 = (const int*)d_in[2];
    const int*   si3 = (const int*)d_in[3];
    float* out = (float*)d_out;

    const int smem_bytes = 2 * BUFSZ * (int)sizeof(float);    // 64512
    cudaFuncSetAttribute(addshift_kernel,
                         cudaFuncAttributeMaxDynamicSharedMemorySize, smem_bytes);

    addshift_kernel<<<GRID, THREADS, smem_bytes>>>(x, si1, si2, si3, out);
}

// round 9
// speedup vs baseline: 1.2109x; 1.0032x over previous
#include <cuda_runtime.h>
#include <cstdint>

#define B_DIM    8
#define C_OUT    64
#define NK       7
#define GROUP_IN 4
#define C_IN     1792              // 64*4*7
#define L_DIM    4096
#define TILE     256
#define HALO     16                // covers |shift| <= 15
#define ROWW     (TILE + 2*HALO)   // 288 floats per staged row
#define ROWB     (ROWW * 4)        // 1152 bytes per staged row
#define NCH      (GROUP_IN * NK)   // 28 channels per c_out
#define THREADS  256
#define GRID     456               // 3 persistent CTAs per GB300 SM
#define NTILES   (B_DIM * C_OUT * (L_DIM / TILE))   // 8192
#define BUFSZ    (NCH * ROWW)      // 8064 floats per buffer
#define BUFB     (BUFSZ * 4)       // 32256 bytes per buffer

// --- TMA bulk 1D: global -> shared, mbarrier transaction-counted ---
__device__ __forceinline__ void bulk_g2s(uint32_t dst, const void* src,
                                         unsigned bytes, uint32_t mbar) {
    asm volatile(
        "cp.async.bulk.shared::cluster.global.mbarrier::complete_tx::bytes "
        "[%0], [%1], %2, [%3];"
        :: "r"(dst), "l"(src), "r"(bytes), "r"(mbar) : "memory");
}
__device__ __forceinline__ void mbar_init(uint32_t mbar, unsigned cnt) {
    asm volatile("mbarrier.init.shared.b64 [%0], %1;" :: "r"(mbar), "r"(cnt) : "memory");
}
__device__ __forceinline__ void mbar_arrive_expect(uint32_t mbar, unsigned bytes) {
    asm volatile("mbarrier.arrive.expect_tx.shared.b64 _, [%0], %1;"
                 :: "r"(mbar), "r"(bytes) : "memory");
}
__device__ __forceinline__ void mbar_arrive(uint32_t mbar) {
    asm volatile("mbarrier.arrive.shared.b64 _, [%0];" :: "r"(mbar) : "memory");
}
__device__ __forceinline__ void mbar_wait(uint32_t mbar, unsigned ph) {
    asm volatile(
        "{\n\t.reg .pred P;\n\t"
        "LAB_%=:\n\t"
        "mbarrier.try_wait.parity.acquire.cta.shared::cta.b64 P, [%0], %1, 0x989680;\n\t"
        "@P bra.uni DONE_%=;\n\t"
        "bra.uni LAB_%=;\n\t"
        "DONE_%=:\n\t}"
        :: "r"(mbar), "r"(ph) : "memory");
}

__global__ __launch_bounds__(THREADS, 3) void addshift_kernel(
    const float* __restrict__ x,
    const int*   __restrict__ si1,
    const int*   __restrict__ si2,
    const int*   __restrict__ si3,
    float*       __restrict__ out)
{
    extern __shared__ float sm[];                 // [2][NCH][ROWW]
    __shared__ unsigned tab[C_OUT * NCH];         // packed per-(co,lc) offsets
    __shared__ __align__(8) unsigned long long mbar_s[4];  // tmb0 tmb1 cmb0 cmb1

    const int tid = threadIdx.x;
    const uint32_t sm_base = (uint32_t)__cvta_generic_to_shared(sm);
    const uint32_t tmb0 = (uint32_t)__cvta_generic_to_shared(&mbar_s[0]);
    const uint32_t tmb1 = (uint32_t)__cvta_generic_to_shared(&mbar_s[1]);
    const uint32_t cmb0 = (uint32_t)__cvta_generic_to_shared(&mbar_s[2]);
    const uint32_t cmb1 = (uint32_t)__cvta_generic_to_shared(&mbar_s[3]);

    // ---- one-time offset table: in-row byte offset = (1 + 5*(idx%7))*4 ----
    for (int c = tid; c < C_IN; c += THREADS) {
        int g  = c / (C_OUT * NK);
        int r  = c - g * (C_OUT * NK);
        int co = r / NK;
        int k  = r - co * NK;
        int lc = g * NK + k;
        unsigned o1 = 4u + 20u * (unsigned)(si1[c] % NK);
        unsigned o2 = 4u + 20u * (unsigned)(si2[c] % NK);
        unsigned o3 = 4u + 20u * (unsigned)(si3[c] % NK);
        tab[co * NCH + lc] = o1 | (o2 << 8) | (o3 << 16);
    }
    if (tid == 0) {
        mbar_init(tmb0, 32);  mbar_init(tmb1, 32);     // warp-0 lanes
        mbar_init(cmb0, THREADS); mbar_init(cmb1, THREADS);
    }
    // per-lane staged-row constant (valid for tid < 28; harmless otherwise)
    const int crel = ((tid / NK) * (C_OUT * NK) + tid % NK) * L_DIM;
    __syncthreads();   // tables + mbarrier init visible; last bar.sync in kernel

    const size_t OSZ = (size_t)B_DIM * C_OUT * L_DIM;   // one output tensor

    // ---- stage one tile into a slot (CALL ONLY FROM WARP 0) ----
    auto stage = [&](int w, uint32_t smslot, uint32_t mb) {
        const int b   = w >> 10;
        const int rem = w & 1023;
        const int co  = rem >> 4;
        const int tx  = rem & 15;
        const bool front = (tx == 0);
        const bool back  = (tx == 15);
        // zero the 16-float OOB halo (bytes disjoint from the bulk copy)
        if (front | back) {
            uint32_t zb = smslot + (front ? 0u : (unsigned)((TILE + HALO) * 4));
            for (int i = tid; i < NCH * 4; i += 32) {          // 112 float4 chunks
                uint32_t a = zb + (unsigned)(i >> 2) * ROWB + (unsigned)(i & 3) * 16u;
                asm volatile("st.shared.v4.b32 [%0], {%1,%1,%1,%1};"
                             :: "r"(a), "r"(0) : "memory");
            }
        }
        const unsigned sz = (front | back) ? (ROWB - 64u) : (unsigned)ROWB;
        // all 32 lanes arrive (releases the STS zeros); lane 0 adds expect_tx
        if (tid == 0) mbar_arrive_expect(mb, NCH * sz);
        else          mbar_arrive(mb);
        if (tid < NCH) {
            const int gstart = (tx << 8) - HALO;
            const float* src = x + ((size_t)b * C_IN + (size_t)co * NK) * L_DIM
                             + crel + gstart + (front ? HALO : 0);
            bulk_g2s(smslot + (uint32_t)tid * ROWB + (front ? 64u : 0u), src, sz, mb);
        }
    };

    // ---- accumulate one tile from a slot; thread owns t = t0 + tid ----
    auto accum = [&](int w, int slot) {
        const int b   = w >> 10;
        const int rem = w & 1023;
        const int co  = rem >> 4;
        const int tx  = rem & 15;
        const unsigned* tabco = tab + co * NCH;
        const char* smb = (const char*)(sm + slot * BUFSZ)
                        + (size_t)((unsigned)tid * 4u);
        float a1 = 0.f, a2 = 0.f, a3 = 0.f;
        #pragma unroll
        for (int lc = 0; lc < NCH; ++lc) {
            unsigned p = tabco[lc];                    // one LDS.32 broadcast
            a1 += *(const float*)(smb + (p & 255u)        + lc * ROWB);
            a2 += *(const float*)(smb + ((p >> 8) & 255u) + lc * ROWB);
            a3 += *(const float*)(smb + (p >> 16)         + lc * ROWB);
        }
        const size_t ob = ((size_t)b * C_OUT + co) * L_DIM + (tx << 8) + tid;
        out[ob]           = a1;
        out[ob + OSZ]     = a2;
        out[ob + 2 * OSZ] = a3;
    };

    // ---- prologue: stage first tile into slot 0 ----
    int w = blockIdx.x;
    if (tid < 32) stage(w, sm_base, tmb0);

    unsigned tph0 = 0, tph1 = 0, cph0 = 0, cph1 = 0;
    bool first1 = true;

    while (true) {
        // ===== slot 0 tile w; stage w+GRID -> slot 1 =====
        int wn = w + GRID;
        if (wn < NTILES) {
            if (tid < 32) {
                if (!first1) { mbar_wait(cmb1, cph1); cph1 ^= 1; }   // slot1 free?
                stage(wn, sm_base + BUFB, tmb1);
            }
            first1 = false;
        }
        mbar_wait(tmb0, tph0); tph0 ^= 1;      // slot0 data landed (acquire)
        accum(w, 0);
        mbar_arrive(cmb0);                     // done reading slot0
        w = wn;
        if (w >= NTILES) break;

        // ===== slot 1 tile w; stage w+GRID -> slot 0 =====
        wn = w + GRID;
        if (wn < NTILES) {
            if (tid < 32) {
                mbar_wait(cmb0, cph0); cph0 ^= 1;                    // slot0 free?
                stage(wn, sm_base, tmb0);
            }
        }
        mbar_wait(tmb1, tph1); tph1 ^= 1;      // slot1 data landed
        accum(w, 1);
        mbar_arrive(cmb1);                     // done reading slot1
        w = wn;
        if (w >= NTILES) break;
    }
}

extern "C" void kernel_launch(void* const* d_in, const int* in_sizes, int n_in,
                              void* d_out, int out_size) {
    const float* x   = (const float*)d_in[0];
    const int*   si1 = (const int*)d_in[1];
    const int*   si2 = (const int*)d_in[2];
    const int*   si3 = (const int*)d_in[3];
    float* out = (float*)d_out;

    const int smem_bytes = 2 * BUFB;          // 64512
    cudaFuncSetAttribute(addshift_kernel,
                         cudaFuncAttributeMaxDynamicSharedMemorySize, smem_bytes);

    addshift_kernel<<<GRID, THREADS, smem_bytes>>>(x, si1, si2, si3, out);
}